// round 12
// baseline (speedup 1.0000x reference)
#include <cuda_runtime.h>
#include <cuda_bf16.h>
#include <math.h>

#define BB   128
#define SS   1024
#define TT   257
#define VV   256
#define EE   128
#define HH   512
#define GG   2048
#define DSTEPS 256
#define NCTA 128
#define NTH  512
#define WPAD 516
#define HB   (HH * BB)

typedef unsigned long long ull;

// ---------------- device globals ----------------
__device__ float g_tabE[VV * GG];
__device__ float g_tabD[VV * GG];
__device__ float g_b1e[GG];
__device__ float g_b1d[GG];
__device__ float g_fcT[HH * VV];                 // [k][v]
__device__ float g_y0T[(size_t)SS * HB];         // encoder L0 outputs, [s][u][b]
__device__ float g_h0TA[HB], g_h0TB[HB];
__device__ float g_h1TA[HB], g_h1TB[HB];
__device__ float g_h1[BB * HH];                  // plain layout for fc
__device__ int   g_tok[BB];
__device__ int   g_cnt[8];
__device__ int   g_gcnt;
__device__ int   g_gen;

// ---------------- helpers ----------------
__device__ __forceinline__ ull pk2(float lo, float hi) {
    ull r; asm("mov.b64 %0, {%1, %2};" : "=l"(r) : "f"(lo), "f"(hi)); return r;
}
__device__ __forceinline__ void fma2(ull& d, ull a, ull b) {
    asm("fma.rn.f32x2 %0, %1, %2, %0;" : "+l"(d) : "l"(a), "l"(b));
}
// L2-scope 16B load (bypasses L1 line allocation; coherent across gbar like cp.async.cg)
__device__ __forceinline__ void ldcg2(ull& a, ull& b, const float* p) {
    asm("ld.global.cg.v2.u64 {%0, %1}, [%2];" : "=l"(a), "=l"(b) : "l"(p));
}

// two-level grid barrier: 8 groups x 16 CTAs
__device__ __forceinline__ void gbar() {
    __syncthreads();
    if (threadIdx.x == 0) {
        const int grp = blockIdx.x >> 4;
        volatile int* vgen = &g_gen;
        int gen = *vgen;
        __threadfence();
        if (atomicAdd(&g_cnt[grp], 1) == 15) {
            atomicExch(&g_cnt[grp], 0);
            if (atomicAdd(&g_gcnt, 1) == 7) {
                atomicExch(&g_gcnt, 0);
                __threadfence();
                atomicAdd(&g_gen, 1);
            } else {
                while (*vgen == gen) { }
            }
        } else {
            while (*vgen == gen) { }
        }
        __threadfence();
    }
    __syncthreads();
}

// ---------------- init kernels ----------------
__global__ void table_kernel(float* __restrict__ tab,
                             const float* __restrict__ emb,
                             const float* __restrict__ w_ih,
                             const float* __restrict__ b_ih,
                             const float* __restrict__ b_hh) {
    const int v = blockIdx.x;
    __shared__ float es[EE];
    if (threadIdx.x < EE) es[threadIdx.x] = emb[v * EE + threadIdx.x];
    __syncthreads();
    for (int j = threadIdx.x; j < GG; j += blockDim.x) {
        float a = b_ih[j] + b_hh[j];
        const float* w = w_ih + (size_t)j * EE;
#pragma unroll 8
        for (int e = 0; e < EE; e++) a += es[e] * w[e];
        tab[(size_t)v * GG + j] = a;
    }
}

__global__ void misc_init_kernel(const int* __restrict__ trg,
                                 const float* __restrict__ be_ih1, const float* __restrict__ be_hh1,
                                 const float* __restrict__ bd_ih1, const float* __restrict__ bd_hh1,
                                 const float* __restrict__ fc_w) {
    const int tid = blockIdx.x * blockDim.x + threadIdx.x;
    const int n = gridDim.x * blockDim.x;
    for (int i = tid; i < HB; i += n) {
        g_h0TA[i] = 0.f; g_h0TB[i] = 0.f;
        g_h1TA[i] = 0.f; g_h1TB[i] = 0.f;
    }
    for (int j = tid; j < GG; j += n) {
        g_b1e[j] = be_ih1[j] + be_hh1[j];
        g_b1d[j] = bd_ih1[j] + bd_hh1[j];
    }
    for (int i = tid; i < HH * VV; i += n) {
        int k = i >> 8, v = i & 255;
        g_fcT[i] = fc_w[v * HH + k];
    }
    for (int b = tid; b < BB; b += n) g_tok[b] = trg[b * TT];
}

// ============================================================
// Geometry (R7): CTA = 4 units (16 gate-cols) x 128 rows.
// 512 threads = 2 K-halves x 8 warps; warp = 16 rows x 16 cols;
// thread = 8 rows x 1 col. A-operand read DIRECTLY from L2 via
// ld.global.cg (no smem staging). Weights cached in smem.
// ============================================================

// smem offsets (floats) — no A-staging buffer anymore
#define S_W0   0
#define S_WX   8256      // 16*516
#define S_WH   16512
#define S_GB   24768     // 2 x 16 x 130 = 4160
#define S_CS0  28928     // 512
#define S_CS1  29440     // 512
#define S_TKS  29952     // 128 ints
#define S_TOTAL 30080

__device__ __forceinline__ void load_wslice(float* dst, const float* __restrict__ W, int u0) {
    for (int idx = threadIdx.x; idx < 16 * HH; idx += NTH) {
        int c = idx >> 9, k = idx & 511;
        int j = (c >> 2) * HH + u0 + (c & 3);
        dst[c * WPAD + k] = W[(size_t)j * HH + k];
    }
}

// partial GEMM over this thread's 256-k half, A read straight from global (L2).
// thread: 8 rows x 1 col; rows at srcT[k*128 + w16 + lrb8 + {0..7}]
__device__ __forceinline__ void mma256_ldg(const float* __restrict__ srcT,
                                           const float* __restrict__ Wsm,
                                           ull acc[4],
                                           int w16, int lrb8, int cg, int koff) {
    const float* wp = Wsm + cg * WPAD + koff;
    const float* ap = srcT + (size_t)koff * 128 + w16 + lrb8;
#pragma unroll 2
    for (int k4 = 0; k4 < 64; k4++) {
        float4 wv = *(const float4*)&wp[k4 * 4];
#pragma unroll
        for (int kk = 0; kk < 4; kk++) {
            const float* p = ap + (size_t)(k4 * 4 + kk) * 128;
            ull qa0, qa1, qb0, qb1;
            ldcg2(qa0, qa1, p);
            ldcg2(qb0, qb1, p + 4);
            float w = (kk == 0) ? wv.x : (kk == 1) ? wv.y : (kk == 2) ? wv.z : wv.w;
            ull w2 = pk2(w, w);
            fma2(acc[0], qa0, w2);
            fma2(acc[1], qa1, w2);
            fma2(acc[2], qb0, w2);
            fma2(acc[3], qb1, w2);
        }
    }
}

template<bool HAS_TOK, bool HAS_X, bool WRITE_PLAIN>
__device__ __forceinline__ void lstm_step(float* smraw,
                                          const float* __restrict__ tab,
                                          const float* __restrict__ bias,
                                          const float* __restrict__ xT,
                                          const float* __restrict__ Wx,
                                          const float* __restrict__ hT,
                                          const float* __restrict__ Wh,
                                          float* __restrict__ cs,
                                          float* __restrict__ hT_out,
                                          float* __restrict__ h_plain,
                                          int u0) {
    float* gbuf = smraw + S_GB;
    int*   tks  = (int*)(smraw + S_TKS);

    const int tid  = threadIdx.x;
    const int wg   = tid >> 8;            // K-half group: 0 or 1
    const int t8   = tid & 255;
    const int rg   = t8 >> 4, cg = t8 & 15;
    const int r0   = rg * 8;
    const int lrb8 = (rg & 1) * 8;
    const int w16  = (t8 >> 5) * 16;
    const int koff = wg * 256;
    const int jc   = (cg >> 2) * HH + u0 + (cg & 3);

    ull acc[4];
    if (wg == 0) {
        if (HAS_TOK) {
#pragma unroll
            for (int rp = 0; rp < 4; rp++) {
                int ta = tks[r0 + 2 * rp];
                int tb = tks[r0 + 2 * rp + 1];
                acc[rp] = pk2(tab[(size_t)ta * GG + jc], tab[(size_t)tb * GG + jc]);
            }
        } else {
            float bv = bias[jc];
            ull b2 = pk2(bv, bv);
#pragma unroll
            for (int rp = 0; rp < 4; rp++) acc[rp] = b2;
        }
    } else {
#pragma unroll
        for (int rp = 0; rp < 4; rp++) acc[rp] = 0ULL;
    }

    if (HAS_X) mma256_ldg(xT, Wx, acc, w16, lrb8, cg, koff);
    mma256_ldg(hT, Wh, acc, w16, lrb8, cg, koff);

#pragma unroll
    for (int rp = 0; rp < 4; rp++)
        *(ull*)&gbuf[wg * 2080 + cg * 130 + r0 + 2 * rp] = acc[rp];
    __syncthreads();

    const int b = tid & 127;
    const int uu = tid >> 7;
    {
        float gi = gbuf[(0 * 4 + uu) * 130 + b] + gbuf[2080 + (0 * 4 + uu) * 130 + b];
        float gf = gbuf[(1 * 4 + uu) * 130 + b] + gbuf[2080 + (1 * 4 + uu) * 130 + b];
        float gg = gbuf[(2 * 4 + uu) * 130 + b] + gbuf[2080 + (2 * 4 + uu) * 130 + b];
        float go = gbuf[(3 * 4 + uu) * 130 + b] + gbuf[2080 + (3 * 4 + uu) * 130 + b];
        float cold = cs[uu * 128 + b];
        float ig = 1.f / (1.f + expf(-gi));
        float fg = 1.f / (1.f + expf(-gf));
        float og = 1.f / (1.f + expf(-go));
        float cn = fg * cold + ig * tanhf(gg);
        float hn = og * tanhf(cn);
        cs[uu * 128 + b] = cn;
        hT_out[(u0 + uu) * 128 + b] = hn;
        if (WRITE_PLAIN) h_plain[b * HH + u0 + uu] = hn;
    }
    __syncthreads();
}

__device__ __forceinline__ void fc_step(float* smraw, int t,
                                        const float* __restrict__ fc_b,
                                        float* __restrict__ out) {
    float* gbuf = smraw + S_GB;
    const int b = blockIdx.x;
    const int tid = threadIdx.x;
    float* h1s  = gbuf;
    float* part = gbuf + 512;
    float* rv   = gbuf + 1024;
    int*   ri   = (int*)(gbuf + 1024 + 256);

    h1s[tid] = g_h1[b * HH + tid];
    __syncthreads();

    const int v = tid & 255;
    const int half = tid >> 8;
    float acc = half ? 0.f : fc_b[v];
    const int k0 = half * 256;
#pragma unroll 8
    for (int k = k0; k < k0 + 256; k++) acc += h1s[k] * g_fcT[k * VV + v];
    part[half * 256 + v] = acc;
    __syncthreads();

    if (tid < 256) {
        float tot = part[tid] + part[256 + tid];
        out[((size_t)b * DSTEPS + t) * VV + tid] = tot;
        rv[tid] = tot; ri[tid] = tid;
    }
    __syncthreads();
    for (int offs = 128; offs > 0; offs >>= 1) {
        if (tid < offs) {
            float o = rv[tid + offs]; int oi = ri[tid + offs];
            if (o > rv[tid] || (o == rv[tid] && oi < ri[tid])) { rv[tid] = o; ri[tid] = oi; }
        }
        __syncthreads();
    }
    if (tid == 0) g_tok[b] = ri[0];
    __syncthreads();
}

// ---------------- the persistent kernel ----------------
__global__ void __launch_bounds__(NTH, 1)
seq2seq_persistent(const int* __restrict__ src,
                   const float* __restrict__ eWhh0,
                   const float* __restrict__ eWih1, const float* __restrict__ eWhh1,
                   const float* __restrict__ dWhh0,
                   const float* __restrict__ dWih1, const float* __restrict__ dWhh1,
                   const float* __restrict__ fc_b,
                   float* __restrict__ out) {
    extern __shared__ float smraw[];
    const int tid = threadIdx.x;
    const int u0 = blockIdx.x * 4;

    // preload all three encoder weight slices; zero both cell states
    load_wslice(smraw + S_W0, eWhh0, u0);
    load_wslice(smraw + S_WX, eWih1, u0);
    load_wslice(smraw + S_WH, eWhh1, u0);
    for (int i = tid; i < 1024; i += NTH) smraw[S_CS0 + i] = 0.f;   // cs0 + cs1
    __syncthreads();

    // ===== fused encoder: L0 step tau + L1 step tau-1 per gbar interval =====
    const float* h0cur = g_h0TA;                 // zeros
    float* h1cur = g_h1TA;                       // zeros
    float* h1nxt = g_h1TB;
    for (int tau = 0; tau <= SS; tau++) {
        if (tau < SS) {
            if (tid < BB) ((int*)(smraw + S_TKS))[tid] = src[tid * SS + tau];
            __syncthreads();
            float* yT = g_y0T + (size_t)tau * HB;
            lstm_step<true, false, false>(smraw, g_tabE, nullptr, nullptr, nullptr,
                                          h0cur, smraw + S_W0, smraw + S_CS0, yT, nullptr, u0);
            h0cur = yT;
        }
        if (tau >= 1) {
            const float* xT = g_y0T + (size_t)(tau - 1) * HB;
            lstm_step<false, true, false>(smraw, nullptr, g_b1e, xT, smraw + S_WX,
                                          h1cur, smraw + S_WH, smraw + S_CS1, h1nxt, nullptr, u0);
            float* tt = h1cur; h1cur = h1nxt; h1nxt = tt;
        }
        gbar();
    }

    // ===== decoder (same geometry; cell states persist in smem) =====
    load_wslice(smraw + S_W0, dWhh0, u0);
    load_wslice(smraw + S_WX, dWih1, u0);
    load_wslice(smraw + S_WH, dWhh1, u0);
    __syncthreads();

    const float* h0c = g_y0T + (size_t)(SS - 1) * HB;   // encoder L0 final h
    float* h0bufs[2] = { g_h0TA, g_h0TB };
    for (int t = 0; t < DSTEPS; t++) {
        if (tid < BB) ((int*)(smraw + S_TKS))[tid] = g_tok[tid];
        __syncthreads();
        float* h0nxt = h0bufs[t & 1];
        lstm_step<true, false, false>(smraw, g_tabD, nullptr, nullptr, nullptr,
                                      h0c, smraw + S_W0, smraw + S_CS0, h0nxt, nullptr, u0);
        gbar();
        lstm_step<false, true, true>(smraw, nullptr, g_b1d, h0nxt, smraw + S_WX,
                                     h1cur, smraw + S_WH, smraw + S_CS1, h1nxt, g_h1, u0);
        gbar();
        fc_step(smraw, t, fc_b, out);
        gbar();
        h0c = h0nxt;
        float* tt = h1cur; h1cur = h1nxt; h1nxt = tt;
    }
}

// ---------------- host launch ----------------
extern "C" void kernel_launch(void* const* d_in, const int* in_sizes, int n_in,
                              void* d_out, int out_size) {
    const int*   src       = (const int*)d_in[0];
    const int*   trg       = (const int*)d_in[1];
    const float* enc_emb   = (const float*)d_in[2];
    const float* enc_w_ih0 = (const float*)d_in[3];
    const float* enc_w_hh0 = (const float*)d_in[4];
    const float* enc_b_ih0 = (const float*)d_in[5];
    const float* enc_b_hh0 = (const float*)d_in[6];
    const float* enc_w_ih1 = (const float*)d_in[7];
    const float* enc_w_hh1 = (const float*)d_in[8];
    const float* enc_b_ih1 = (const float*)d_in[9];
    const float* enc_b_hh1 = (const float*)d_in[10];
    const float* dec_emb   = (const float*)d_in[11];
    const float* dec_w_ih0 = (const float*)d_in[12];
    const float* dec_w_hh0 = (const float*)d_in[13];
    const float* dec_b_ih0 = (const float*)d_in[14];
    const float* dec_b_hh0 = (const float*)d_in[15];
    const float* dec_w_ih1 = (const float*)d_in[16];
    const float* dec_w_hh1 = (const float*)d_in[17];
    const float* dec_b_ih1 = (const float*)d_in[18];
    const float* dec_b_hh1 = (const float*)d_in[19];
    const float* fc_w      = (const float*)d_in[20];
    const float* fc_b      = (const float*)d_in[21];
    float* out = (float*)d_out;

    float* tabE; cudaGetSymbolAddress((void**)&tabE, g_tabE);
    float* tabD; cudaGetSymbolAddress((void**)&tabD, g_tabD);

    static int smem_set = 0;
    const int SMEM_BYTES = S_TOTAL * 4;   // ~117.5 KB
    if (!smem_set) {
        cudaFuncSetAttribute(seq2seq_persistent,
                             cudaFuncAttributeMaxDynamicSharedMemorySize, SMEM_BYTES);
        smem_set = 1;
    }

    table_kernel<<<VV, 256>>>(tabE, enc_emb, enc_w_ih0, enc_b_ih0, enc_b_hh0);
    table_kernel<<<VV, 256>>>(tabD, dec_emb, dec_w_ih0, dec_b_ih0, dec_b_hh0);
    misc_init_kernel<<<256, 256>>>(trg, enc_b_ih1, enc_b_hh1, dec_b_ih1, dec_b_hh1, fc_w);

    seq2seq_persistent<<<NCTA, NTH, SMEM_BYTES>>>(
        src, enc_w_hh0, enc_w_ih1, enc_w_hh1,
        dec_w_hh0, dec_w_ih1, dec_w_hh1, fc_b, out);

    (void)in_sizes; (void)n_in; (void)out_size;
}

// round 13
// speedup vs baseline: 1.3976x; 1.3976x over previous
#include <cuda_runtime.h>
#include <cuda_bf16.h>
#include <math.h>

#define BB   128
#define SS   1024
#define TT   257
#define VV   256
#define EE   128
#define HH   512
#define GG   2048
#define DSTEPS 256
#define NCTA 128
#define NTH  512
#define WPAD 516
#define HB   (HH * BB)
#define CHUNK_K      64
#define CHUNK_FLOATS (CHUNK_K * 128)      // 8192
#define CHUNK_BYTES  (CHUNK_FLOATS * 4)   // 32768

typedef unsigned long long ull;

// ---------------- device globals ----------------
__device__ float g_tabE[VV * GG];
__device__ float g_tabD[VV * GG];
__device__ float g_b1e[GG];
__device__ float g_b1d[GG];
__device__ float g_fcT[HH * VV];                 // [k][v]
__device__ float g_y0T[(size_t)SS * HB];         // encoder L0 outputs, [s][u][b]
__device__ float g_h0TA[HB], g_h0TB[HB];
__device__ float g_h1TA[HB], g_h1TB[HB];
__device__ float g_h1[BB * HH];                  // plain layout for fc
__device__ int   g_tok[BB];
__device__ int   g_cnt[8];
__device__ int   g_gcnt;
__device__ int   g_gen;

// ---------------- helpers ----------------
__device__ __forceinline__ ull pk2(float lo, float hi) {
    ull r; asm("mov.b64 %0, {%1, %2};" : "=l"(r) : "f"(lo), "f"(hi)); return r;
}
__device__ __forceinline__ void fma2(ull& d, ull a, ull b) {
    asm("fma.rn.f32x2 %0, %1, %2, %0;" : "+l"(d) : "l"(a), "l"(b));
}
__device__ __forceinline__ unsigned scvta(const void* p) {
    return (unsigned)__cvta_generic_to_shared(p);
}
// one-shot bulk copy global->smem with mbarrier completion
__device__ __forceinline__ void bulk_cp(unsigned dst_smem, const float* src, unsigned mbar) {
    asm volatile(
        "cp.async.bulk.shared::cta.global.mbarrier::complete_tx::bytes [%0], [%1], %2, [%3];"
        :: "r"(dst_smem), "l"(src), "r"((unsigned)CHUNK_BYTES), "r"(mbar) : "memory");
}
__device__ __forceinline__ void mb_init(unsigned mbar, unsigned count) {
    asm volatile("mbarrier.init.shared.b64 [%0], %1;" :: "r"(mbar), "r"(count) : "memory");
}
__device__ __forceinline__ void mb_expect(unsigned mbar, unsigned bytes) {
    asm volatile("mbarrier.arrive.expect_tx.shared.b64 _, [%0], %1;"
                 :: "r"(mbar), "r"(bytes) : "memory");
}
__device__ __forceinline__ void mb_wait(unsigned mbar, unsigned parity) {
    asm volatile(
        "{\n\t.reg .pred P;\n"
        "WL%=:\n\t"
        "mbarrier.try_wait.parity.acquire.cta.shared::cta.b64 P, [%0], %1, 0x989680;\n\t"
        "@!P bra WL%=;\n\t}"
        :: "r"(mbar), "r"(parity) : "memory");
}

// two-level grid barrier: 8 groups x 16 CTAs
__device__ __forceinline__ void gbar() {
    __syncthreads();
    if (threadIdx.x == 0) {
        const int grp = blockIdx.x >> 4;
        volatile int* vgen = &g_gen;
        int gen = *vgen;
        __threadfence();
        if (atomicAdd(&g_cnt[grp], 1) == 15) {
            atomicExch(&g_cnt[grp], 0);
            if (atomicAdd(&g_gcnt, 1) == 7) {
                atomicExch(&g_gcnt, 0);
                __threadfence();
                atomicAdd(&g_gen, 1);
            } else {
                while (*vgen == gen) { }
            }
        } else {
            while (*vgen == gen) { }
        }
        __threadfence();
    }
    __syncthreads();
}

// ---------------- init kernels ----------------
__global__ void table_kernel(float* __restrict__ tab,
                             const float* __restrict__ emb,
                             const float* __restrict__ w_ih,
                             const float* __restrict__ b_ih,
                             const float* __restrict__ b_hh) {
    const int v = blockIdx.x;
    __shared__ float es[EE];
    if (threadIdx.x < EE) es[threadIdx.x] = emb[v * EE + threadIdx.x];
    __syncthreads();
    for (int j = threadIdx.x; j < GG; j += blockDim.x) {
        float a = b_ih[j] + b_hh[j];
        const float* w = w_ih + (size_t)j * EE;
#pragma unroll 8
        for (int e = 0; e < EE; e++) a += es[e] * w[e];
        tab[(size_t)v * GG + j] = a;
    }
}

__global__ void misc_init_kernel(const int* __restrict__ trg,
                                 const float* __restrict__ be_ih1, const float* __restrict__ be_hh1,
                                 const float* __restrict__ bd_ih1, const float* __restrict__ bd_hh1,
                                 const float* __restrict__ fc_w) {
    const int tid = blockIdx.x * blockDim.x + threadIdx.x;
    const int n = gridDim.x * blockDim.x;
    for (int i = tid; i < HB; i += n) {
        g_h0TA[i] = 0.f; g_h0TB[i] = 0.f;
        g_h1TA[i] = 0.f; g_h1TB[i] = 0.f;
    }
    for (int j = tid; j < GG; j += n) {
        g_b1e[j] = be_ih1[j] + be_hh1[j];
        g_b1d[j] = bd_ih1[j] + bd_hh1[j];
    }
    for (int i = tid; i < HH * VV; i += n) {
        int k = i >> 8, v = i & 255;
        g_fcT[i] = fc_w[v * HH + k];
    }
    for (int b = tid; b < BB; b += n) g_tok[b] = trg[b * TT];
}

// ============================================================
// Geometry: CTA = 4 units (16 gate-cols) x 128 rows; 512 threads,
// thread = 4 rows x 1 col, full K=512. A staged CTA-wide by
// cp.async.bulk (thread 0) into a 2x32KB double buffer.
// ============================================================

// smem offsets (floats)
#define S_W0   0
#define S_WX   8256      // 16*516
#define S_WH   16512
#define S_AS   24768     // 2 x 8192 = 16384
#define S_GB   41152     // 16 x 130 = 2080
#define S_CS0  43232     // 512
#define S_CS1  43744     // 512
#define S_TKS  44256     // 128 ints
#define S_MB   44384     // 2 mbarriers (16 bytes)
#define S_TOTAL 44392

struct Pipe { unsigned p0, p1; };

__device__ __forceinline__ void load_wslice(float* dst, const float* __restrict__ W, int u0) {
    for (int idx = threadIdx.x; idx < 16 * HH; idx += NTH) {
        int c = idx >> 9, k = idx & 511;
        int j = (c >> 2) * HH + u0 + (c & 3);
        dst[c * WPAD + k] = W[(size_t)j * HH + k];
    }
}

// GEMM over K=512: 8 bulk-copied chunks of 64k x 128b, double buffered.
// thread: 4 rows x 1 col.
__device__ __forceinline__ void mma512_bulk(const float* __restrict__ srcT,
                                            const float* __restrict__ Wsm,
                                            float* As, unsigned mb0, unsigned mb1,
                                            Pipe& pp, ull acc[2],
                                            int r0, int cg, int tid) {
    const float* wp = Wsm + cg * WPAD;
    const unsigned as0 = scvta(As);
    const unsigned as1 = scvta(As + CHUNK_FLOATS);
    if (tid == 0) {
        mb_expect(mb0, CHUNK_BYTES);
        bulk_cp(as0, srcT, mb0);
    }
#pragma unroll
    for (int ch = 0; ch < 8; ch++) {
        if (ch < 7 && tid == 0) {
            unsigned mbn = ((ch + 1) & 1) ? mb1 : mb0;
            mb_expect(mbn, CHUNK_BYTES);
            bulk_cp(((ch + 1) & 1) ? as1 : as0, srcT + (size_t)(ch + 1) * CHUNK_FLOATS, mbn);
        }
        if (ch & 1) { mb_wait(mb1, pp.p1); pp.p1 ^= 1; }
        else        { mb_wait(mb0, pp.p0); pp.p0 ^= 1; }
        const float* cur = As + (ch & 1) * CHUNK_FLOATS;
#pragma unroll
        for (int k4 = 0; k4 < 16; k4++) {
            float4 wv = *(const float4*)&wp[ch * 64 + k4 * 4];
#pragma unroll
            for (int kk = 0; kk < 4; kk++) {
                int ko = k4 * 4 + kk;
                ulonglong2 qa = *(const ulonglong2*)&cur[ko * 128 + r0];
                float w = (kk == 0) ? wv.x : (kk == 1) ? wv.y : (kk == 2) ? wv.z : wv.w;
                ull w2 = pk2(w, w);
                fma2(acc[0], qa.x, w2);
                fma2(acc[1], qa.y, w2);
            }
        }
        __syncthreads();   // buffer reuse fence
    }
}

template<bool HAS_TOK, bool HAS_X, bool WRITE_PLAIN>
__device__ __forceinline__ void lstm_step(float* smraw, Pipe& pp,
                                          const float* __restrict__ tab,
                                          const float* __restrict__ bias,
                                          const float* __restrict__ xT,
                                          const float* __restrict__ Wx,
                                          const float* __restrict__ hT,
                                          const float* __restrict__ Wh,
                                          float* __restrict__ cs,
                                          float* __restrict__ hT_out,
                                          float* __restrict__ h_plain,
                                          int u0) {
    float* As   = smraw + S_AS;
    float* gbuf = smraw + S_GB;
    int*   tks  = (int*)(smraw + S_TKS);
    const unsigned mb0 = scvta(smraw + S_MB);
    const unsigned mb1 = scvta(smraw + S_MB + 2);

    const int tid = threadIdx.x;
    const int rg  = tid >> 4;            // 0..31 row-groups of 4
    const int cg  = tid & 15;            // gate-col
    const int r0  = rg * 4;
    const int jc  = (cg >> 2) * HH + u0 + (cg & 3);

    ull acc[2];
    if (HAS_TOK) {
        int t0 = tks[r0],     t1 = tks[r0 + 1];
        int t2 = tks[r0 + 2], t3 = tks[r0 + 3];
        acc[0] = pk2(tab[(size_t)t0 * GG + jc], tab[(size_t)t1 * GG + jc]);
        acc[1] = pk2(tab[(size_t)t2 * GG + jc], tab[(size_t)t3 * GG + jc]);
    } else {
        float bv = bias[jc];
        ull b2 = pk2(bv, bv);
        acc[0] = b2; acc[1] = b2;
    }

    if (HAS_X) mma512_bulk(xT, Wx, As, mb0, mb1, pp, acc, r0, cg, tid);
    mma512_bulk(hT, Wh, As, mb0, mb1, pp, acc, r0, cg, tid);

    *(ull*)&gbuf[cg * 130 + r0]     = acc[0];
    *(ull*)&gbuf[cg * 130 + r0 + 2] = acc[1];
    __syncthreads();

    const int b = tid & 127;
    const int uu = tid >> 7;
    {
        float gi = gbuf[(0 * 4 + uu) * 130 + b];
        float gf = gbuf[(1 * 4 + uu) * 130 + b];
        float gg = gbuf[(2 * 4 + uu) * 130 + b];
        float go = gbuf[(3 * 4 + uu) * 130 + b];
        float cold = cs[uu * 128 + b];
        float ig = 1.f / (1.f + expf(-gi));
        float fg = 1.f / (1.f + expf(-gf));
        float og = 1.f / (1.f + expf(-go));
        float cn = fg * cold + ig * tanhf(gg);
        float hn = og * tanhf(cn);
        cs[uu * 128 + b] = cn;
        hT_out[(u0 + uu) * 128 + b] = hn;
        if (WRITE_PLAIN) h_plain[b * HH + u0 + uu] = hn;
    }
    __syncthreads();
}

__device__ __forceinline__ void fc_step(float* smraw, int t,
                                        const float* __restrict__ fc_b,
                                        float* __restrict__ out) {
    float* gbuf = smraw + S_GB;
    const int b = blockIdx.x;
    const int tid = threadIdx.x;
    float* h1s  = gbuf;
    float* part = gbuf + 512;
    float* rv   = gbuf + 1024;
    int*   ri   = (int*)(gbuf + 1024 + 256);

    h1s[tid] = g_h1[b * HH + tid];
    __syncthreads();

    const int v = tid & 255;
    const int half = tid >> 8;
    float acc = half ? 0.f : fc_b[v];
    const int k0 = half * 256;
#pragma unroll 8
    for (int k = k0; k < k0 + 256; k++) acc += h1s[k] * g_fcT[k * VV + v];
    part[half * 256 + v] = acc;
    __syncthreads();

    if (tid < 256) {
        float tot = part[tid] + part[256 + tid];
        out[((size_t)b * DSTEPS + t) * VV + tid] = tot;
        rv[tid] = tot; ri[tid] = tid;
    }
    __syncthreads();
    for (int offs = 128; offs > 0; offs >>= 1) {
        if (tid < offs) {
            float o = rv[tid + offs]; int oi = ri[tid + offs];
            if (o > rv[tid] || (o == rv[tid] && oi < ri[tid])) { rv[tid] = o; ri[tid] = oi; }
        }
        __syncthreads();
    }
    if (tid == 0) g_tok[b] = ri[0];
    __syncthreads();
}

// ---------------- the persistent kernel ----------------
__global__ void __launch_bounds__(NTH, 1)
seq2seq_persistent(const int* __restrict__ src,
                   const float* __restrict__ eWhh0,
                   const float* __restrict__ eWih1, const float* __restrict__ eWhh1,
                   const float* __restrict__ dWhh0,
                   const float* __restrict__ dWih1, const float* __restrict__ dWhh1,
                   const float* __restrict__ fc_b,
                   float* __restrict__ out) {
    extern __shared__ float smraw[];
    const int tid = threadIdx.x;
    const int u0 = blockIdx.x * 4;

    // init mbarriers + preload encoder weights + zero cell states
    if (tid == 0) {
        mb_init(scvta(smraw + S_MB), 1);
        mb_init(scvta(smraw + S_MB + 2), 1);
    }
    load_wslice(smraw + S_W0, eWhh0, u0);
    load_wslice(smraw + S_WX, eWih1, u0);
    load_wslice(smraw + S_WH, eWhh1, u0);
    for (int i = tid; i < 1024; i += NTH) smraw[S_CS0 + i] = 0.f;   // cs0 + cs1
    __syncthreads();

    Pipe pp; pp.p0 = 0; pp.p1 = 0;

    // ===== fused encoder: L0 step tau + L1 step tau-1 per gbar interval =====
    const float* h0cur = g_h0TA;                 // zeros
    float* h1cur = g_h1TA;                       // zeros
    float* h1nxt = g_h1TB;
    for (int tau = 0; tau <= SS; tau++) {
        if (tau < SS) {
            if (tid < BB) ((int*)(smraw + S_TKS))[tid] = src[tid * SS + tau];
            __syncthreads();
            float* yT = g_y0T + (size_t)tau * HB;
            lstm_step<true, false, false>(smraw, pp, g_tabE, nullptr, nullptr, nullptr,
                                          h0cur, smraw + S_W0, smraw + S_CS0, yT, nullptr, u0);
            h0cur = yT;
        }
        if (tau >= 1) {
            const float* xT = g_y0T + (size_t)(tau - 1) * HB;
            lstm_step<false, true, false>(smraw, pp, nullptr, g_b1e, xT, smraw + S_WX,
                                          h1cur, smraw + S_WH, smraw + S_CS1, h1nxt, nullptr, u0);
            float* tt = h1cur; h1cur = h1nxt; h1nxt = tt;
        }
        gbar();
    }

    // ===== decoder (same geometry; cell states persist in smem) =====
    load_wslice(smraw + S_W0, dWhh0, u0);
    load_wslice(smraw + S_WX, dWih1, u0);
    load_wslice(smraw + S_WH, dWhh1, u0);
    __syncthreads();

    const float* h0c = g_y0T + (size_t)(SS - 1) * HB;   // encoder L0 final h
    float* h0bufs[2] = { g_h0TA, g_h0TB };
    for (int t = 0; t < DSTEPS; t++) {
        if (tid < BB) ((int*)(smraw + S_TKS))[tid] = g_tok[tid];
        __syncthreads();
        float* h0nxt = h0bufs[t & 1];
        lstm_step<true, false, false>(smraw, pp, g_tabD, nullptr, nullptr, nullptr,
                                      h0c, smraw + S_W0, smraw + S_CS0, h0nxt, nullptr, u0);
        gbar();
        lstm_step<false, true, true>(smraw, pp, nullptr, g_b1d, h0nxt, smraw + S_WX,
                                     h1cur, smraw + S_WH, smraw + S_CS1, h1nxt, g_h1, u0);
        gbar();
        fc_step(smraw, t, fc_b, out);
        gbar();
        h0c = h0nxt;
        float* tt = h1cur; h1cur = h1nxt; h1nxt = tt;
    }
}

// ---------------- host launch ----------------
extern "C" void kernel_launch(void* const* d_in, const int* in_sizes, int n_in,
                              void* d_out, int out_size) {
    const int*   src       = (const int*)d_in[0];
    const int*   trg       = (const int*)d_in[1];
    const float* enc_emb   = (const float*)d_in[2];
    const float* enc_w_ih0 = (const float*)d_in[3];
    const float* enc_w_hh0 = (const float*)d_in[4];
    const float* enc_b_ih0 = (const float*)d_in[5];
    const float* enc_b_hh0 = (const float*)d_in[6];
    const float* enc_w_ih1 = (const float*)d_in[7];
    const float* enc_w_hh1 = (const float*)d_in[8];
    const float* enc_b_ih1 = (const float*)d_in[9];
    const float* enc_b_hh1 = (const float*)d_in[10];
    const float* dec_emb   = (const float*)d_in[11];
    const float* dec_w_ih0 = (const float*)d_in[12];
    const float* dec_w_hh0 = (const float*)d_in[13];
    const float* dec_b_ih0 = (const float*)d_in[14];
    const float* dec_b_hh0 = (const float*)d_in[15];
    const float* dec_w_ih1 = (const float*)d_in[16];
    const float* dec_w_hh1 = (const float*)d_in[17];
    const float* dec_b_ih1 = (const float*)d_in[18];
    const float* dec_b_hh1 = (const float*)d_in[19];
    const float* fc_w      = (const float*)d_in[20];
    const float* fc_b      = (const float*)d_in[21];
    float* out = (float*)d_out;

    float* tabE; cudaGetSymbolAddress((void**)&tabE, g_tabE);
    float* tabD; cudaGetSymbolAddress((void**)&tabD, g_tabD);

    static int smem_set = 0;
    const int SMEM_BYTES = S_TOTAL * 4;   // ~173.4 KB
    if (!smem_set) {
        cudaFuncSetAttribute(seq2seq_persistent,
                             cudaFuncAttributeMaxDynamicSharedMemorySize, SMEM_BYTES);
        smem_set = 1;
    }

    table_kernel<<<VV, 256>>>(tabE, enc_emb, enc_w_ih0, enc_b_ih0, enc_b_hh0);
    table_kernel<<<VV, 256>>>(tabD, dec_emb, dec_w_ih0, dec_b_ih0, dec_b_hh0);
    misc_init_kernel<<<256, 256>>>(trg, enc_b_ih1, enc_b_hh1, dec_b_ih1, dec_b_hh1, fc_w);

    seq2seq_persistent<<<NCTA, NTH, SMEM_BYTES>>>(
        src, enc_w_hh0, enc_w_ih1, enc_w_hh1,
        dec_w_hh0, dec_w_ih1, dec_w_hh1, fc_b, out);

    (void)in_sizes; (void)n_in; (void)out_size;
}

// round 14
// speedup vs baseline: 1.5283x; 1.0935x over previous
#include <cuda_runtime.h>
#include <cuda_bf16.h>
#include <math.h>

#define BB   128
#define SS   1024
#define TT   257
#define VV   256
#define EE   128
#define HH   512
#define GG   2048
#define DSTEPS 256
#define NCTA 128
#define NTH  512
#define WPAD 516
#define HB   (HH * BB)
#define XSLICE (16 * 128)     // per-CTA per-step xg slice (16 cols x 128 batch)

typedef unsigned long long ull;

// ---------------- device globals ----------------
__device__ float g_tabE[VV * GG];
__device__ float g_tabD[VV * GG];
__device__ float g_b1e[GG];
__device__ float g_b1d[GG];
__device__ float g_fcT[HH * VV];                 // [k][v]
__device__ float g_y0T[(size_t)SS * HB];         // encoder L0 outputs, [s][u][b]
__device__ float g_xg[(size_t)SS * NCTA * XSLICE]; // 1 GB: precomputed L1 input gates
__device__ float g_h0TA[HB], g_h0TB[HB];
__device__ float g_h1TA[HB], g_h1TB[HB];
__device__ float g_h1[BB * HH];                  // plain layout for fc
__device__ int   g_tok[BB];
__device__ int   g_cnt[8];
__device__ int   g_gcnt;
__device__ int   g_gen;

// ---------------- helpers ----------------
__device__ __forceinline__ ull pk2(float lo, float hi) {
    ull r; asm("mov.b64 %0, {%1, %2};" : "=l"(r) : "f"(lo), "f"(hi)); return r;
}
__device__ __forceinline__ void fma2(ull& d, ull a, ull b) {
    asm("fma.rn.f32x2 %0, %1, %2, %0;" : "+l"(d) : "l"(a), "l"(b));
}
__device__ __forceinline__ void cp16(float* dst_smem, const float* src) {
    unsigned s = (unsigned)__cvta_generic_to_shared(dst_smem);
    asm volatile("cp.async.cg.shared.global [%0], [%1], 16;" :: "r"(s), "l"(src));
}
#define CP_COMMIT() asm volatile("cp.async.commit_group;")
#define CP_WAIT0()  asm volatile("cp.async.wait_group 0;")
#define CP_WAIT1()  asm volatile("cp.async.wait_group 1;")

// two-level grid barrier: 8 groups x 16 CTAs
__device__ __forceinline__ void gbar() {
    __syncthreads();
    if (threadIdx.x == 0) {
        const int grp = blockIdx.x >> 4;
        volatile int* vgen = &g_gen;
        int gen = *vgen;
        __threadfence();
        if (atomicAdd(&g_cnt[grp], 1) == 15) {
            atomicExch(&g_cnt[grp], 0);
            if (atomicAdd(&g_gcnt, 1) == 7) {
                atomicExch(&g_gcnt, 0);
                __threadfence();
                atomicAdd(&g_gen, 1);
            } else {
                while (*vgen == gen) { }
            }
        } else {
            while (*vgen == gen) { }
        }
        __threadfence();
    }
    __syncthreads();
}

// ---------------- init kernels ----------------
__global__ void table_kernel(float* __restrict__ tab,
                             const float* __restrict__ emb,
                             const float* __restrict__ w_ih,
                             const float* __restrict__ b_ih,
                             const float* __restrict__ b_hh) {
    const int v = blockIdx.x;
    __shared__ float es[EE];
    if (threadIdx.x < EE) es[threadIdx.x] = emb[v * EE + threadIdx.x];
    __syncthreads();
    for (int j = threadIdx.x; j < GG; j += blockDim.x) {
        float a = b_ih[j] + b_hh[j];
        const float* w = w_ih + (size_t)j * EE;
#pragma unroll 8
        for (int e = 0; e < EE; e++) a += es[e] * w[e];
        tab[(size_t)v * GG + j] = a;
    }
}

__global__ void misc_init_kernel(const int* __restrict__ trg,
                                 const float* __restrict__ be_ih1, const float* __restrict__ be_hh1,
                                 const float* __restrict__ bd_ih1, const float* __restrict__ bd_hh1,
                                 const float* __restrict__ fc_w) {
    const int tid = blockIdx.x * blockDim.x + threadIdx.x;
    const int n = gridDim.x * blockDim.x;
    for (int i = tid; i < HB; i += n) {
        g_h0TA[i] = 0.f; g_h0TB[i] = 0.f;
        g_h1TA[i] = 0.f; g_h1TB[i] = 0.f;
    }
    for (int j = tid; j < GG; j += n) {
        g_b1e[j] = be_ih1[j] + be_hh1[j];
        g_b1d[j] = bd_ih1[j] + bd_hh1[j];
    }
    for (int i = tid; i < HH * VV; i += n) {
        int k = i >> 8, v = i & 255;
        g_fcT[i] = fc_w[v * HH + k];
    }
    for (int b = tid; b < BB; b += n) g_tok[b] = trg[b * TT];
}

// ============================================================
// Geometry (R7): CTA = 4 units (16 gate-cols) x 128 rows.
// 512 threads = 2 K-halves x 8 warps; warp = 16 rows x 16 cols;
// thread = 8 rows x 1 col. Per-warp autonomous cp.async staging.
// ============================================================

// smem offsets (floats)
#define S_W0   0
#define S_WX   8256      // 16*516
#define S_WH   16512
#define S_AS   24768     // 16 warps x 2 bufs x 512 = 16384
#define S_GB   41152     // 2 x 16 x 130 = 4160
#define S_CS0  45312     // 512
#define S_CS1  45824     // 512
#define S_TKS  46336     // 128 ints
#define S_TOTAL 46464

__device__ __forceinline__ void load_wslice(float* dst, const float* __restrict__ W, int u0) {
    for (int idx = threadIdx.x; idx < 16 * HH; idx += NTH) {
        int c = idx >> 9, k = idx & 511;
        int j = (c >> 2) * HH + u0 + (c & 3);
        dst[c * WPAD + k] = W[(size_t)j * HH + k];
    }
}

__device__ __forceinline__ void stage_u4(float* dst, const float* __restrict__ srcT,
                                         int kbase, int lane, int w16) {
#pragma unroll
    for (int i = 0; i < 4; i++) {
        int idx = i * 32 + lane;
        int k = idx >> 2, jq = idx & 3;
        cp16(dst + k * 16 + jq * 4, srcT + (size_t)(kbase + k) * 128 + w16 + jq * 4);
    }
}

__device__ __forceinline__ void mma256_u4(const float* __restrict__ srcT,
                                          const float* __restrict__ Wsm,
                                          float* wbuf, ull acc[4],
                                          int lane, int w16, int lrb8, int cg, int koff) {
    const float* wp = Wsm + cg * WPAD + koff;
    stage_u4(wbuf, srcT, koff, lane, w16);
    CP_COMMIT();
#pragma unroll 1
    for (int ch = 0; ch < 8; ch++) {
        const float* cur = wbuf + (ch & 1) * 512;
        if (ch < 7) {
            stage_u4(wbuf + ((ch + 1) & 1) * 512, srcT, koff + (ch + 1) * 32, lane, w16);
            CP_COMMIT();
            CP_WAIT1();
        } else {
            CP_WAIT0();
        }
        __syncwarp();
#pragma unroll
        for (int k4 = 0; k4 < 8; k4++) {
            float4 wv = *(const float4*)&wp[ch * 32 + k4 * 4];
#pragma unroll
            for (int kk = 0; kk < 4; kk++) {
                int ko = k4 * 4 + kk;
                ulonglong2 qa = *(const ulonglong2*)&cur[ko * 16 + lrb8];
                ulonglong2 qb = *(const ulonglong2*)&cur[ko * 16 + lrb8 + 4];
                float w = (kk == 0) ? wv.x : (kk == 1) ? wv.y : (kk == 2) ? wv.z : wv.w;
                ull w2 = pk2(w, w);
                fma2(acc[0], qa.x, w2);
                fma2(acc[1], qa.y, w2);
                fma2(acc[2], qb.x, w2);
                fma2(acc[3], qb.y, w2);
            }
        }
        __syncwarp();
    }
}

// INIT: 0 = token table, 1 = bias, 2 = precomputed xg slice
// OUT_XG: write raw gate pre-activations to xg_out instead of state update
template<int INIT, bool HAS_X, bool OUT_XG, bool WRITE_PLAIN>
__device__ __forceinline__ void lstm_step(float* smraw,
                                          const float* __restrict__ tab,
                                          const float* __restrict__ bias,
                                          const float* __restrict__ xg_in,
                                          const float* __restrict__ xT,
                                          const float* __restrict__ Wx,
                                          const float* __restrict__ hT,
                                          const float* __restrict__ Wh,
                                          float* __restrict__ cs,
                                          float* __restrict__ hT_out,
                                          float* __restrict__ h_plain,
                                          float* __restrict__ xg_out,
                                          int u0) {
    float* As   = smraw + S_AS;
    float* gbuf = smraw + S_GB;
    int*   tks  = (int*)(smraw + S_TKS);

    const int tid  = threadIdx.x;
    const int lane = tid & 31;
    const int wg   = tid >> 8;            // K-half group: 0 or 1
    const int t8   = tid & 255;
    const int rg   = t8 >> 4, cg = t8 & 15;
    const int r0   = rg * 8;
    const int lrb8 = (rg & 1) * 8;
    const int w16  = (t8 >> 5) * 16;
    const int koff = wg * 256;
    const int jc   = (cg >> 2) * HH + u0 + (cg & 3);
    float* wbuf = As + (tid >> 5) * 1024;

    ull acc[4];
    if (wg == 0) {
        if (INIT == 0) {
#pragma unroll
            for (int rp = 0; rp < 4; rp++) {
                int ta = tks[r0 + 2 * rp];
                int tb = tks[r0 + 2 * rp + 1];
                acc[rp] = pk2(tab[(size_t)ta * GG + jc], tab[(size_t)tb * GG + jc]);
            }
        } else if (INIT == 1) {
            float bv = bias[jc];
            ull b2 = pk2(bv, bv);
#pragma unroll
            for (int rp = 0; rp < 4; rp++) acc[rp] = b2;
        } else {
#pragma unroll
            for (int rp = 0; rp < 4; rp++)
                acc[rp] = *(const ull*)&xg_in[cg * 128 + r0 + 2 * rp];
        }
    } else {
#pragma unroll
        for (int rp = 0; rp < 4; rp++) acc[rp] = 0ULL;
    }

    if (HAS_X) mma256_u4(xT, Wx, wbuf, acc, lane, w16, lrb8, cg, koff);
    mma256_u4(hT, Wh, wbuf, acc, lane, w16, lrb8, cg, koff);

#pragma unroll
    for (int rp = 0; rp < 4; rp++)
        *(ull*)&gbuf[wg * 2080 + cg * 130 + r0 + 2 * rp] = acc[rp];
    __syncthreads();

    const int b = tid & 127;
    const int uu = tid >> 7;
    {
        float gi = gbuf[(0 * 4 + uu) * 130 + b] + gbuf[2080 + (0 * 4 + uu) * 130 + b];
        float gf = gbuf[(1 * 4 + uu) * 130 + b] + gbuf[2080 + (1 * 4 + uu) * 130 + b];
        float gg = gbuf[(2 * 4 + uu) * 130 + b] + gbuf[2080 + (2 * 4 + uu) * 130 + b];
        float go = gbuf[(3 * 4 + uu) * 130 + b] + gbuf[2080 + (3 * 4 + uu) * 130 + b];
        if (OUT_XG) {
            xg_out[(0 * 4 + uu) * 128 + b] = gi;
            xg_out[(1 * 4 + uu) * 128 + b] = gf;
            xg_out[(2 * 4 + uu) * 128 + b] = gg;
            xg_out[(3 * 4 + uu) * 128 + b] = go;
        } else {
            float cold = cs[uu * 128 + b];
            float ig = 1.f / (1.f + expf(-gi));
            float fg = 1.f / (1.f + expf(-gf));
            float og = 1.f / (1.f + expf(-go));
            float cn = fg * cold + ig * tanhf(gg);
            float hn = og * tanhf(cn);
            cs[uu * 128 + b] = cn;
            hT_out[(u0 + uu) * 128 + b] = hn;
            if (WRITE_PLAIN) h_plain[b * HH + u0 + uu] = hn;
        }
    }
    __syncthreads();
}

__device__ __forceinline__ void fc_step(float* smraw, int t,
                                        const float* __restrict__ fc_b,
                                        float* __restrict__ out) {
    float* gbuf = smraw + S_GB;
    const int b = blockIdx.x;
    const int tid = threadIdx.x;
    float* h1s  = gbuf;
    float* part = gbuf + 512;
    float* rv   = gbuf + 1024;
    int*   ri   = (int*)(gbuf + 1024 + 256);

    h1s[tid] = g_h1[b * HH + tid];
    __syncthreads();

    const int v = tid & 255;
    const int half = tid >> 8;
    float acc = half ? 0.f : fc_b[v];
    const int k0 = half * 256;
#pragma unroll 8
    for (int k = k0; k < k0 + 256; k++) acc += h1s[k] * g_fcT[k * VV + v];
    part[half * 256 + v] = acc;
    __syncthreads();

    if (tid < 256) {
        float tot = part[tid] + part[256 + tid];
        out[((size_t)b * DSTEPS + t) * VV + tid] = tot;
        rv[tid] = tot; ri[tid] = tid;
    }
    __syncthreads();
    for (int offs = 128; offs > 0; offs >>= 1) {
        if (tid < offs) {
            float o = rv[tid + offs]; int oi = ri[tid + offs];
            if (o > rv[tid] || (o == rv[tid] && oi < ri[tid])) { rv[tid] = o; ri[tid] = oi; }
        }
        __syncthreads();
    }
    if (tid == 0) g_tok[b] = ri[0];
    __syncthreads();
}

// ---------------- the persistent kernel ----------------
__global__ void __launch_bounds__(NTH, 1)
seq2seq_persistent(const int* __restrict__ src,
                   const float* __restrict__ eWhh0,
                   const float* __restrict__ eWih1, const float* __restrict__ eWhh1,
                   const float* __restrict__ dWhh0,
                   const float* __restrict__ dWih1, const float* __restrict__ dWhh1,
                   const float* __restrict__ fc_b,
                   float* __restrict__ out) {
    extern __shared__ float smraw[];
    const int tid = threadIdx.x;
    const int cta = blockIdx.x;
    const int u0 = cta * 4;

    load_wslice(smraw + S_W0, eWhh0, u0);
    load_wslice(smraw + S_WX, eWih1, u0);
    load_wslice(smraw + S_WH, eWhh1, u0);
    for (int i = tid; i < 1024; i += NTH) smraw[S_CS0 + i] = 0.f;   // cs0 + cs1
    __syncthreads();

    // ===== phase 1: encoder L0 recurrence (barriered) =====
    {
        const float* h0cur = g_h0TA;   // zeros
        for (int s = 0; s < SS; s++) {
            if (tid < BB) ((int*)(smraw + S_TKS))[tid] = src[tid * SS + s];
            __syncthreads();
            float* yT = g_y0T + (size_t)s * HB;
            lstm_step<0, false, false, false>(smraw, g_tabE, nullptr, nullptr,
                                              nullptr, nullptr, h0cur, smraw + S_W0,
                                              smraw + S_CS0, yT, nullptr, nullptr, u0);
            h0cur = yT;
            gbar();
        }
    }

    // ===== phase 2: STREAMED xg = y0 @ Wih1 + b1e  (no grid barriers!) =====
    // Each CTA computes and later consumes its OWN 16-column slice -> local ordering only.
#pragma unroll 1
    for (int s = 0; s < SS; s++) {
        const float* yT = g_y0T + (size_t)s * HB;
        float* xg_out = g_xg + ((size_t)s * NCTA + cta) * XSLICE;
        lstm_step<1, false, true, false>(smraw, nullptr, g_b1e, nullptr,
                                         nullptr, nullptr, yT, smraw + S_WX,
                                         nullptr, nullptr, nullptr, xg_out, u0);
    }

    // ===== phase 3: encoder L1 recurrence (h-GEMM only; x-part from xg) =====
    {
        float* h1cur = g_h1TA;        // zeros
        float* h1nxt = g_h1TB;
        for (int s = 0; s < SS; s++) {
            const float* xg_in = g_xg + ((size_t)s * NCTA + cta) * XSLICE;
            lstm_step<2, false, false, false>(smraw, nullptr, nullptr, xg_in,
                                              nullptr, nullptr, h1cur, smraw + S_WH,
                                              smraw + S_CS1, h1nxt, nullptr, nullptr, u0);
            float* tt = h1cur; h1cur = h1nxt; h1nxt = tt;
            gbar();
        }
    }

    // ===== decoder (R7 geometry; cell states persist in smem) =====
    load_wslice(smraw + S_W0, dWhh0, u0);
    load_wslice(smraw + S_WX, dWih1, u0);
    load_wslice(smraw + S_WH, dWhh1, u0);
    __syncthreads();

    const float* h0c = g_y0T + (size_t)(SS - 1) * HB;   // encoder L0 final h
    float* h1cur = g_h1TA;                              // L1 final h (1024 steps even)
    float* h1nxt = g_h1TB;
    float* h0bufs[2] = { g_h0TA, g_h0TB };
    for (int t = 0; t < DSTEPS; t++) {
        if (tid < BB) ((int*)(smraw + S_TKS))[tid] = g_tok[tid];
        __syncthreads();
        float* h0nxt = h0bufs[t & 1];
        lstm_step<0, false, false, false>(smraw, g_tabD, nullptr, nullptr,
                                          nullptr, nullptr, h0c, smraw + S_W0,
                                          smraw + S_CS0, h0nxt, nullptr, nullptr, u0);
        gbar();
        lstm_step<1, true, false, true>(smraw, nullptr, g_b1d, nullptr,
                                        h0nxt, smraw + S_WX, h1cur, smraw + S_WH,
                                        smraw + S_CS1, h1nxt, g_h1, nullptr, u0);
        gbar();
        fc_step(smraw, t, fc_b, out);
        gbar();
        h0c = h0nxt;
        float* tt = h1cur; h1cur = h1nxt; h1nxt = tt;
    }
}

// ---------------- host launch ----------------
extern "C" void kernel_launch(void* const* d_in, const int* in_sizes, int n_in,
                              void* d_out, int out_size) {
    const int*   src       = (const int*)d_in[0];
    const int*   trg       = (const int*)d_in[1];
    const float* enc_emb   = (const float*)d_in[2];
    const float* enc_w_ih0 = (const float*)d_in[3];
    const float* enc_w_hh0 = (const float*)d_in[4];
    const float* enc_b_ih0 = (const float*)d_in[5];
    const float* enc_b_hh0 = (const float*)d_in[6];
    const float* enc_w_ih1 = (const float*)d_in[7];
    const float* enc_w_hh1 = (const float*)d_in[8];
    const float* enc_b_ih1 = (const float*)d_in[9];
    const float* enc_b_hh1 = (const float*)d_in[10];
    const float* dec_emb   = (const float*)d_in[11];
    const float* dec_w_ih0 = (const float*)d_in[12];
    const float* dec_w_hh0 = (const float*)d_in[13];
    const float* dec_b_ih0 = (const float*)d_in[14];
    const float* dec_b_hh0 = (const float*)d_in[15];
    const float* dec_w_ih1 = (const float*)d_in[16];
    const float* dec_w_hh1 = (const float*)d_in[17];
    const float* dec_b_ih1 = (const float*)d_in[18];
    const float* dec_b_hh1 = (const float*)d_in[19];
    const float* fc_w      = (const float*)d_in[20];
    const float* fc_b      = (const float*)d_in[21];
    float* out = (float*)d_out;

    float* tabE; cudaGetSymbolAddress((void**)&tabE, g_tabE);
    float* tabD; cudaGetSymbolAddress((void**)&tabD, g_tabD);

    static int smem_set = 0;
    const int SMEM_BYTES = S_TOTAL * 4;   // ~185.9 KB
    if (!smem_set) {
        cudaFuncSetAttribute(seq2seq_persistent,
                             cudaFuncAttributeMaxDynamicSharedMemorySize, SMEM_BYTES);
        smem_set = 1;
    }

    table_kernel<<<VV, 256>>>(tabE, enc_emb, enc_w_ih0, enc_b_ih0, enc_b_hh0);
    table_kernel<<<VV, 256>>>(tabD, dec_emb, dec_w_ih0, dec_b_ih0, dec_b_hh0);
    misc_init_kernel<<<256, 256>>>(trg, enc_b_ih1, enc_b_hh1, dec_b_ih1, dec_b_hh1, fc_w);

    seq2seq_persistent<<<NCTA, NTH, SMEM_BYTES>>>(
        src, enc_w_hh0, enc_w_ih1, enc_w_hh1,
        dec_w_hh0, dec_w_ih1, dec_w_hh1, fc_b, out);

    (void)in_sizes; (void)n_in; (void)out_size;
}

// round 15
// speedup vs baseline: 1.5334x; 1.0034x over previous
#include <cuda_runtime.h>
#include <cuda_bf16.h>
#include <math.h>

#define BB   128
#define SS   1024
#define TT   257
#define VV   256
#define EE   128
#define HH   512
#define GG   2048
#define DSTEPS 256
#define NCTA 128
#define NTH  512
#define WPAD 516
#define HB   (HH * BB)
#define XSLICE (16 * 128)     // per-CTA per-step xg slice (16 cols x 128 batch)

typedef unsigned long long ull;

// ---------------- device globals ----------------
__device__ float g_tabE[VV * GG];
__device__ float g_tabD[VV * GG];
__device__ float g_b1e[GG];
__device__ float g_b1d[GG];
__device__ float g_fcT[HH * VV];                 // [k][v]
__device__ float g_y0T[(size_t)SS * HB];         // encoder L0 outputs, [s][u][b]
__device__ float g_xg[(size_t)SS * NCTA * XSLICE]; // 1 GB: precomputed L1 input gates
__device__ float g_h0TA[HB], g_h0TB[HB];
__device__ float g_h1TA[HB], g_h1TB[HB];
__device__ float g_h1[BB * HH];                  // plain layout for fc
__device__ int   g_tok[BB];
__device__ int   g_cnt[8];
__device__ int   g_gcnt;
__device__ int   g_gen;

// ---------------- helpers ----------------
__device__ __forceinline__ ull pk2(float lo, float hi) {
    ull r; asm("mov.b64 %0, {%1, %2};" : "=l"(r) : "f"(lo), "f"(hi)); return r;
}
__device__ __forceinline__ void fma2(ull& d, ull a, ull b) {
    asm("fma.rn.f32x2 %0, %1, %2, %0;" : "+l"(d) : "l"(a), "l"(b));
}
__device__ __forceinline__ void cp16(float* dst_smem, const float* src) {
    unsigned s = (unsigned)__cvta_generic_to_shared(dst_smem);
    asm volatile("cp.async.cg.shared.global [%0], [%1], 16;" :: "r"(s), "l"(src));
}
#define CP_COMMIT() asm volatile("cp.async.commit_group;")
#define CP_WAIT0()  asm volatile("cp.async.wait_group 0;")
#define CP_WAIT1()  asm volatile("cp.async.wait_group 1;")

// two-level grid barrier: 8 groups x 16 CTAs
__device__ __forceinline__ void gbar() {
    __syncthreads();
    if (threadIdx.x == 0) {
        const int grp = blockIdx.x >> 4;
        volatile int* vgen = &g_gen;
        int gen = *vgen;
        __threadfence();
        if (atomicAdd(&g_cnt[grp], 1) == 15) {
            atomicExch(&g_cnt[grp], 0);
            if (atomicAdd(&g_gcnt, 1) == 7) {
                atomicExch(&g_gcnt, 0);
                __threadfence();
                atomicAdd(&g_gen, 1);
            } else {
                while (*vgen == gen) { }
            }
        } else {
            while (*vgen == gen) { }
        }
        __threadfence();
    }
    __syncthreads();
}

// ---------------- init kernels ----------------
__global__ void table_kernel(float* __restrict__ tab,
                             const float* __restrict__ emb,
                             const float* __restrict__ w_ih,
                             const float* __restrict__ b_ih,
                             const float* __restrict__ b_hh) {
    const int v = blockIdx.x;
    __shared__ float es[EE];
    if (threadIdx.x < EE) es[threadIdx.x] = emb[v * EE + threadIdx.x];
    __syncthreads();
    for (int j = threadIdx.x; j < GG; j += blockDim.x) {
        float a = b_ih[j] + b_hh[j];
        const float* w = w_ih + (size_t)j * EE;
#pragma unroll 8
        for (int e = 0; e < EE; e++) a += es[e] * w[e];
        tab[(size_t)v * GG + j] = a;
    }
}

__global__ void misc_init_kernel(const int* __restrict__ trg,
                                 const float* __restrict__ be_ih1, const float* __restrict__ be_hh1,
                                 const float* __restrict__ bd_ih1, const float* __restrict__ bd_hh1,
                                 const float* __restrict__ fc_w) {
    const int tid = blockIdx.x * blockDim.x + threadIdx.x;
    const int n = gridDim.x * blockDim.x;
    for (int i = tid; i < HB; i += n) {
        g_h0TA[i] = 0.f; g_h0TB[i] = 0.f;
        g_h1TA[i] = 0.f; g_h1TB[i] = 0.f;
    }
    for (int j = tid; j < GG; j += n) {
        g_b1e[j] = be_ih1[j] + be_hh1[j];
        g_b1d[j] = bd_ih1[j] + bd_hh1[j];
    }
    for (int i = tid; i < HH * VV; i += n) {
        int k = i >> 8, v = i & 255;
        g_fcT[i] = fc_w[v * HH + k];
    }
    for (int b = tid; b < BB; b += n) g_tok[b] = trg[b * TT];
}

// ============================================================
// Geometry (R7): CTA = 4 units (16 gate-cols) x 128 rows.
// 512 threads = 2 K-halves x 8 warps; warp = 16 rows x 16 cols;
// thread = 8 rows x 1 col. Per-warp autonomous cp.async staging.
// ============================================================

// smem offsets (floats)
#define S_W0   0
#define S_WX   8256      // 16*516
#define S_WH   16512
#define S_AS   24768     // 16 warps x 2 bufs x 512 = 16384
#define S_GB   41152     // 2 x 16 x 130 = 4160
#define S_CS0  45312     // 512
#define S_CS1  45824     // 512
#define S_TKS  46336     // 128 ints
#define S_TOTAL 46464

__device__ __forceinline__ void load_wslice(float* dst, const float* __restrict__ W, int u0) {
    for (int idx = threadIdx.x; idx < 16 * HH; idx += NTH) {
        int c = idx >> 9, k = idx & 511;
        int j = (c >> 2) * HH + u0 + (c & 3);
        dst[c * WPAD + k] = W[(size_t)j * HH + k];
    }
}

__device__ __forceinline__ void stage_u4(float* dst, const float* __restrict__ srcT,
                                         int kbase, int lane, int w16) {
#pragma unroll
    for (int i = 0; i < 4; i++) {
        int idx = i * 32 + lane;
        int k = idx >> 2, jq = idx & 3;
        cp16(dst + k * 16 + jq * 4, srcT + (size_t)(kbase + k) * 128 + w16 + jq * 4);
    }
}

__device__ __forceinline__ void mma256_u4(const float* __restrict__ srcT,
                                          const float* __restrict__ Wsm,
                                          float* wbuf, ull acc[4],
                                          int lane, int w16, int lrb8, int cg, int koff) {
    const float* wp = Wsm + cg * WPAD + koff;
    stage_u4(wbuf, srcT, koff, lane, w16);
    CP_COMMIT();
#pragma unroll 1
    for (int ch = 0; ch < 8; ch++) {
        const float* cur = wbuf + (ch & 1) * 512;
        if (ch < 7) {
            stage_u4(wbuf + ((ch + 1) & 1) * 512, srcT, koff + (ch + 1) * 32, lane, w16);
            CP_COMMIT();
            CP_WAIT1();
        } else {
            CP_WAIT0();
        }
        __syncwarp();
#pragma unroll
        for (int k4 = 0; k4 < 8; k4++) {
            float4 wv = *(const float4*)&wp[ch * 32 + k4 * 4];
#pragma unroll
            for (int kk = 0; kk < 4; kk++) {
                int ko = k4 * 4 + kk;
                ulonglong2 qa = *(const ulonglong2*)&cur[ko * 16 + lrb8];
                ulonglong2 qb = *(const ulonglong2*)&cur[ko * 16 + lrb8 + 4];
                float w = (kk == 0) ? wv.x : (kk == 1) ? wv.y : (kk == 2) ? wv.z : wv.w;
                ull w2 = pk2(w, w);
                fma2(acc[0], qa.x, w2);
                fma2(acc[1], qa.y, w2);
                fma2(acc[2], qb.x, w2);
                fma2(acc[3], qb.y, w2);
            }
        }
        __syncwarp();
    }
}

// INIT: 0 = token table, 1 = bias, 2 = precomputed xg slice
// OUT_XG: write raw gate pre-activations to xg_out instead of state update
template<int INIT, bool HAS_X, bool OUT_XG, bool WRITE_PLAIN>
__device__ __forceinline__ void lstm_step(float* smraw,
                                          const float* __restrict__ tab,
                                          const float* __restrict__ bias,
                                          const float* __restrict__ xg_in,
                                          const float* __restrict__ xT,
                                          const float* __restrict__ Wx,
                                          const float* __restrict__ hT,
                                          const float* __restrict__ Wh,
                                          float* __restrict__ cs,
                                          float* __restrict__ hT_out,
                                          float* __restrict__ h_plain,
                                          float* __restrict__ xg_out,
                                          int u0) {
    float* As   = smraw + S_AS;
    float* gbuf = smraw + S_GB;
    int*   tks  = (int*)(smraw + S_TKS);

    const int tid  = threadIdx.x;
    const int lane = tid & 31;
    const int wg   = tid >> 8;            // K-half group: 0 or 1
    const int t8   = tid & 255;
    const int rg   = t8 >> 4, cg = t8 & 15;
    const int r0   = rg * 8;
    const int lrb8 = (rg & 1) * 8;
    const int w16  = (t8 >> 5) * 16;
    const int koff = wg * 256;
    const int jc   = (cg >> 2) * HH + u0 + (cg & 3);
    float* wbuf = As + (tid >> 5) * 1024;

    ull acc[4];
    if (wg == 0) {
        if (INIT == 0) {
#pragma unroll
            for (int rp = 0; rp < 4; rp++) {
                int ta = tks[r0 + 2 * rp];
                int tb = tks[r0 + 2 * rp + 1];
                acc[rp] = pk2(tab[(size_t)ta * GG + jc], tab[(size_t)tb * GG + jc]);
            }
        } else if (INIT == 1) {
            float bv = bias[jc];
            ull b2 = pk2(bv, bv);
#pragma unroll
            for (int rp = 0; rp < 4; rp++) acc[rp] = b2;
        } else {
#pragma unroll
            for (int rp = 0; rp < 4; rp++)
                acc[rp] = *(const ull*)&xg_in[cg * 128 + r0 + 2 * rp];
        }
    } else {
#pragma unroll
        for (int rp = 0; rp < 4; rp++) acc[rp] = 0ULL;
    }

    if (HAS_X) mma256_u4(xT, Wx, wbuf, acc, lane, w16, lrb8, cg, koff);
    mma256_u4(hT, Wh, wbuf, acc, lane, w16, lrb8, cg, koff);

#pragma unroll
    for (int rp = 0; rp < 4; rp++)
        *(ull*)&gbuf[wg * 2080 + cg * 130 + r0 + 2 * rp] = acc[rp];
    __syncthreads();

    const int b = tid & 127;
    const int uu = tid >> 7;
    {
        float gi = gbuf[(0 * 4 + uu) * 130 + b] + gbuf[2080 + (0 * 4 + uu) * 130 + b];
        float gf = gbuf[(1 * 4 + uu) * 130 + b] + gbuf[2080 + (1 * 4 + uu) * 130 + b];
        float gg = gbuf[(2 * 4 + uu) * 130 + b] + gbuf[2080 + (2 * 4 + uu) * 130 + b];
        float go = gbuf[(3 * 4 + uu) * 130 + b] + gbuf[2080 + (3 * 4 + uu) * 130 + b];
        if (OUT_XG) {
            xg_out[(0 * 4 + uu) * 128 + b] = gi;
            xg_out[(1 * 4 + uu) * 128 + b] = gf;
            xg_out[(2 * 4 + uu) * 128 + b] = gg;
            xg_out[(3 * 4 + uu) * 128 + b] = go;
        } else {
            float cold = cs[uu * 128 + b];
            float ig = 1.f / (1.f + expf(-gi));
            float fg = 1.f / (1.f + expf(-gf));
            float og = 1.f / (1.f + expf(-go));
            float cn = fg * cold + ig * tanhf(gg);
            float hn = og * tanhf(cn);
            cs[uu * 128 + b] = cn;
            hT_out[(u0 + uu) * 128 + b] = hn;
            if (WRITE_PLAIN) h_plain[b * HH + u0 + uu] = hn;
        }
    }
    __syncthreads();
}

__device__ __forceinline__ void fc_step(float* smraw, int t,
                                        const float* __restrict__ fc_b,
                                        float* __restrict__ out) {
    float* gbuf = smraw + S_GB;
    const int b = blockIdx.x;
    const int tid = threadIdx.x;
    float* h1s  = gbuf;
    float* part = gbuf + 512;
    float* rv   = gbuf + 1024;
    int*   ri   = (int*)(gbuf + 1024 + 256);

    h1s[tid] = g_h1[b * HH + tid];
    __syncthreads();

    const int v = tid & 255;
    const int half = tid >> 8;
    float acc = half ? 0.f : fc_b[v];
    const int k0 = half * 256;
#pragma unroll 8
    for (int k = k0; k < k0 + 256; k++) acc += h1s[k] * g_fcT[k * VV + v];
    part[half * 256 + v] = acc;
    __syncthreads();

    if (tid < 256) {
        float tot = part[tid] + part[256 + tid];
        out[((size_t)b * DSTEPS + t) * VV + tid] = tot;
        rv[tid] = tot; ri[tid] = tid;
    }
    __syncthreads();
    for (int offs = 128; offs > 0; offs >>= 1) {
        if (tid < offs) {
            float o = rv[tid + offs]; int oi = ri[tid + offs];
            if (o > rv[tid] || (o == rv[tid] && oi < ri[tid])) { rv[tid] = o; ri[tid] = oi; }
        }
        __syncthreads();
    }
    if (tid == 0) g_tok[b] = ri[0];
    __syncthreads();
}

// ---------------- the persistent kernel ----------------
__global__ void __launch_bounds__(NTH, 1)
seq2seq_persistent(const int* __restrict__ src,
                   const float* __restrict__ eWhh0,
                   const float* __restrict__ eWih1, const float* __restrict__ eWhh1,
                   const float* __restrict__ dWhh0,
                   const float* __restrict__ dWih1, const float* __restrict__ dWhh1,
                   const float* __restrict__ fc_b,
                   float* __restrict__ out) {
    extern __shared__ float smraw[];
    const int tid = threadIdx.x;
    const int cta = blockIdx.x;
    const int u0 = cta * 4;

    load_wslice(smraw + S_W0, eWhh0, u0);
    load_wslice(smraw + S_WX, eWih1, u0);
    load_wslice(smraw + S_WH, eWhh1, u0);
    for (int i = tid; i < 1024; i += NTH) smraw[S_CS0 + i] = 0.f;   // cs0 + cs1
    __syncthreads();

    // ===== phase 1: encoder L0 recurrence (barriered) =====
    {
        const float* h0cur = g_h0TA;   // zeros
        for (int s = 0; s < SS; s++) {
            if (tid < BB) ((int*)(smraw + S_TKS))[tid] = src[tid * SS + s];
            __syncthreads();
            float* yT = g_y0T + (size_t)s * HB;
            lstm_step<0, false, false, false>(smraw, g_tabE, nullptr, nullptr,
                                              nullptr, nullptr, h0cur, smraw + S_W0,
                                              smraw + S_CS0, yT, nullptr, nullptr, u0);
            h0cur = yT;
            gbar();
        }
    }

    // ===== phase 2: STREAMED xg = y0 @ Wih1 + b1e  (no grid barriers!) =====
    // Each CTA computes and later consumes its OWN 16-column slice -> local ordering only.
#pragma unroll 1
    for (int s = 0; s < SS; s++) {
        const float* yT = g_y0T + (size_t)s * HB;
        float* xg_out = g_xg + ((size_t)s * NCTA + cta) * XSLICE;
        lstm_step<1, false, true, false>(smraw, nullptr, g_b1e, nullptr,
                                         nullptr, nullptr, yT, smraw + S_WX,
                                         nullptr, nullptr, nullptr, xg_out, u0);
    }

    // ===== phase 3: encoder L1 recurrence (h-GEMM only; x-part from xg) =====
    {
        float* h1cur = g_h1TA;        // zeros
        float* h1nxt = g_h1TB;
        for (int s = 0; s < SS; s++) {
            const float* xg_in = g_xg + ((size_t)s * NCTA + cta) * XSLICE;
            lstm_step<2, false, false, false>(smraw, nullptr, nullptr, xg_in,
                                              nullptr, nullptr, h1cur, smraw + S_WH,
                                              smraw + S_CS1, h1nxt, nullptr, nullptr, u0);
            float* tt = h1cur; h1cur = h1nxt; h1nxt = tt;
            gbar();
        }
    }

    // ===== decoder (R7 geometry; cell states persist in smem) =====
    load_wslice(smraw + S_W0, dWhh0, u0);
    load_wslice(smraw + S_WX, dWih1, u0);
    load_wslice(smraw + S_WH, dWhh1, u0);
    __syncthreads();

    const float* h0c = g_y0T + (size_t)(SS - 1) * HB;   // encoder L0 final h
    float* h1cur = g_h1TA;                              // L1 final h (1024 steps even)
    float* h1nxt = g_h1TB;
    float* h0bufs[2] = { g_h0TA, g_h0TB };
    for (int t = 0; t < DSTEPS; t++) {
        if (tid < BB) ((int*)(smraw + S_TKS))[tid] = g_tok[tid];
        __syncthreads();
        float* h0nxt = h0bufs[t & 1];
        lstm_step<0, false, false, false>(smraw, g_tabD, nullptr, nullptr,
                                          nullptr, nullptr, h0c, smraw + S_W0,
                                          smraw + S_CS0, h0nxt, nullptr, nullptr, u0);
        gbar();
        lstm_step<1, true, false, true>(smraw, nullptr, g_b1d, nullptr,
                                        h0nxt, smraw + S_WX, h1cur, smraw + S_WH,
                                        smraw + S_CS1, h1nxt, g_h1, nullptr, u0);
        gbar();
        fc_step(smraw, t, fc_b, out);
        gbar();
        h0c = h0nxt;
        float* tt = h1cur; h1cur = h1nxt; h1nxt = tt;
    }
}

// ---------------- host launch ----------------
extern "C" void kernel_launch(void* const* d_in, const int* in_sizes, int n_in,
                              void* d_out, int out_size) {
    const int*   src       = (const int*)d_in[0];
    const int*   trg       = (const int*)d_in[1];
    const float* enc_emb   = (const float*)d_in[2];
    const float* enc_w_ih0 = (const float*)d_in[3];
    const float* enc_w_hh0 = (const float*)d_in[4];
    const float* enc_b_ih0 = (const float*)d_in[5];
    const float* enc_b_hh0 = (const float*)d_in[6];
    const float* enc_w_ih1 = (const float*)d_in[7];
    const float* enc_w_hh1 = (const float*)d_in[8];
    const float* enc_b_ih1 = (const float*)d_in[9];
    const float* enc_b_hh1 = (const float*)d_in[10];
    const float* dec_emb   = (const float*)d_in[11];
    const float* dec_w_ih0 = (const float*)d_in[12];
    const float* dec_w_hh0 = (const float*)d_in[13];
    const float* dec_b_ih0 = (const float*)d_in[14];
    const float* dec_b_hh0 = (const float*)d_in[15];
    const float* dec_w_ih1 = (const float*)d_in[16];
    const float* dec_w_hh1 = (const float*)d_in[17];
    const float* dec_b_ih1 = (const float*)d_in[18];
    const float* dec_b_hh1 = (const float*)d_in[19];
    const float* fc_w      = (const float*)d_in[20];
    const float* fc_b      = (const float*)d_in[21];
    float* out = (float*)d_out;

    float* tabE; cudaGetSymbolAddress((void**)&tabE, g_tabE);
    float* tabD; cudaGetSymbolAddress((void**)&tabD, g_tabD);

    static int smem_set = 0;
    const int SMEM_BYTES = S_TOTAL * 4;   // ~185.9 KB
    if (!smem_set) {
        cudaFuncSetAttribute(seq2seq_persistent,
                             cudaFuncAttributeMaxDynamicSharedMemorySize, SMEM_BYTES);
        smem_set = 1;
    }

    table_kernel<<<VV, 256>>>(tabE, enc_emb, enc_w_ih0, enc_b_ih0, enc_b_hh0);
    table_kernel<<<VV, 256>>>(tabD, dec_emb, dec_w_ih0, dec_b_ih0, dec_b_hh0);
    misc_init_kernel<<<256, 256>>>(trg, enc_b_ih1, enc_b_hh1, dec_b_ih1, dec_b_hh1, fc_w);

    seq2seq_persistent<<<NCTA, NTH, SMEM_BYTES>>>(
        src, enc_w_hh0, enc_w_ih1, enc_w_hh1,
        dec_w_hh0, dec_w_ih1, dec_w_hh1, fc_b, out);

    (void)in_sizes; (void)n_in; (void)out_size;
}